// round 1
// baseline (speedup 1.0000x reference)
#include <cuda_runtime.h>

#define BB   8
#define C    256
#define CI   128
#define NSP  3136
#define NCH  49
#define CHS  64
#define PN   4096

// ---------------- scratch (device globals; no allocations) ----------------
__device__ float d_u[C], d_v[C], d_inv[C], d_obias[C];
__device__ float d_ca, d_cb;
__device__ float d_gwT[C * CI];                       // g_w transposed [c][o]
__device__ float d_gx[(size_t)BB * NSP * CI];         // g_x [b][n][o]
__device__ float d_av[BB * NSP], d_bvv[BB * NSP];     // a (incl consts), b
__device__ float d_bsort[BB * NSP];
__device__ int   d_perm[BB * NSP];
__device__ int   d_lbi[BB * NSP];
__device__ float d_cs0[BB * NCH * CI], d_cs1[BB * NCH * CI];
__device__ float d_S0[(size_t)BB * (NSP + 1) * CI];
__device__ float d_S1[(size_t)BB * (NSP + 1) * CI];
__device__ float d_y[(size_t)BB * NSP * CI];

// ---------------- prep: fold theta/phi/wf into vectors, fold BN ----------------
__global__ void k_prep(const float* __restrict__ theta_w, const float* __restrict__ theta_b,
                       const float* __restrict__ phi_w,   const float* __restrict__ phi_b,
                       const float* __restrict__ wf_w,    const float* __restrict__ wf_b,
                       const float* __restrict__ wz_b,    const float* __restrict__ gamma_,
                       const float* __restrict__ beta_,   const float* __restrict__ mean_,
                       const float* __restrict__ var_)
{
    int c = threadIdx.x;  // 0..255
    float u = 0.f, v = 0.f;
    for (int o = 0; o < CI; o++) {
        u = fmaf(wf_w[o],      theta_w[o * C + c], u);
        v = fmaf(wf_w[CI + o], phi_w[o * C + c],   v);
    }
    d_u[c] = u; d_v[c] = v;
    float iv = gamma_[c] / sqrtf(var_[c] + 1e-5f);
    d_inv[c]   = iv;
    d_obias[c] = (wz_b[c] - mean_[c]) * iv + beta_[c];
    if (c == 0) {
        float ca = 0.f, cb = 0.f;
        for (int o = 0; o < CI; o++) {
            ca = fmaf(wf_w[o],      theta_b[o], ca);
            cb = fmaf(wf_w[CI + o], phi_b[o],   cb);
        }
        d_ca = ca + wf_b[0];   // t_i = u.x_i + d_ca  (includes wf_b)
        d_cb = cb;             // b_j = v.x_j + d_cb
    }
}

__global__ void k_tr(const float* __restrict__ g_w)
{
    int idx = blockIdx.x * 256 + threadIdx.x;   // 32768 = C*CI
    int c = idx / CI, o = idx % CI;
    d_gwT[idx] = g_w[o * C + c];
}

// ---------------- a/b per position ----------------
__global__ void k_ab(const float* __restrict__ x)
{
    int b = blockIdx.y;
    int n = blockIdx.x * blockDim.x + threadIdx.x;
    if (n >= NSP) return;
    const float* xp = x + (size_t)b * C * NSP + n;
    float a = d_ca, bb = d_cb;
#pragma unroll 8
    for (int c = 0; c < C; c++) {
        float xv = xp[(size_t)c * NSP];
        a  = fmaf(d_u[c], xv, a);
        bb = fmaf(d_v[c], xv, bb);
    }
    d_av[b * NSP + n]  = a;
    d_bvv[b * NSP + n] = bb;
}

// ---------------- g_x GEMM: g_x[b,n,o] = sum_c g_w[o,c] x[b,c,n] + g_b[o] ----------------
__global__ void k_gemm1(const float* __restrict__ x, const float* __restrict__ g_b)
{
    __shared__ float gs[16][CI];   // [k][o]
    __shared__ float xs[16][64];   // [k][nn]
    int b = blockIdx.y;
    int n0 = blockIdx.x * 64;
    int tid = threadIdx.x, lane = tid & 31, warp = tid >> 5;
    float acc[4][8];
#pragma unroll
    for (int i = 0; i < 4; i++)
#pragma unroll
        for (int j = 0; j < 8; j++) acc[i][j] = 0.f;

    for (int c0 = 0; c0 < C; c0 += 16) {
        for (int idx = tid; idx < 16 * CI; idx += 256) {
            int k = idx >> 7, o = idx & 127;
            gs[k][o] = d_gwT[(c0 + k) * CI + o];
        }
        for (int idx = tid; idx < 16 * 64; idx += 256) {
            int k = idx >> 6, nn = idx & 63;
            xs[k][nn] = x[((size_t)b * C + c0 + k) * NSP + n0 + nn];
        }
        __syncthreads();
#pragma unroll
        for (int k = 0; k < 16; k++) {
            float4 g4 = *reinterpret_cast<const float4*>(&gs[k][lane * 4]);
            float xv[8];
#pragma unroll
            for (int j = 0; j < 8; j++) xv[j] = xs[k][warp * 8 + j];
#pragma unroll
            for (int j = 0; j < 8; j++) {
                acc[0][j] = fmaf(g4.x, xv[j], acc[0][j]);
                acc[1][j] = fmaf(g4.y, xv[j], acc[1][j]);
                acc[2][j] = fmaf(g4.z, xv[j], acc[2][j]);
                acc[3][j] = fmaf(g4.w, xv[j], acc[3][j]);
            }
        }
        __syncthreads();
    }
    float4 bias = *reinterpret_cast<const float4*>(&g_b[lane * 4]);
#pragma unroll
    for (int j = 0; j < 8; j++) {
        int n = n0 + warp * 8 + j;
        float4 r = make_float4(acc[0][j] + bias.x, acc[1][j] + bias.y,
                               acc[2][j] + bias.z, acc[3][j] + bias.w);
        *reinterpret_cast<float4*>(&d_gx[((size_t)b * NSP + n) * CI + lane * 4]) = r;
    }
}

// ---------------- sort b values per batch (bitonic, padded to 4096) ----------------
__global__ void k_sort()
{
    __shared__ float key[PN];
    __shared__ int   idx[PN];
    int b = blockIdx.x;
    for (int e = threadIdx.x; e < PN; e += blockDim.x) {
        key[e] = (e < NSP) ? d_bvv[b * NSP + e] : 3.4e38f;
        idx[e] = e;
    }
    __syncthreads();
    for (int k = 2; k <= PN; k <<= 1) {
        for (int j = k >> 1; j > 0; j >>= 1) {
            for (int e = threadIdx.x; e < PN; e += blockDim.x) {
                int ixj = e ^ j;
                if (ixj > e) {
                    bool up = ((e & k) == 0);
                    float ka = key[e], kb = key[ixj];
                    if (up ? (ka > kb) : (ka < kb)) {
                        key[e] = kb; key[ixj] = ka;
                        int t = idx[e]; idx[e] = idx[ixj]; idx[ixj] = t;
                    }
                }
            }
            __syncthreads();
        }
    }
    for (int e = threadIdx.x; e < NSP; e += blockDim.x) {
        d_bsort[b * NSP + e] = key[e];
        d_perm[b * NSP + e]  = idx[e];
    }
}

// ---------------- suffix sums of gathered g_x (chunked scan) ----------------
__global__ void k_suf1()
{
    int b = blockIdx.y, ch = blockIdx.x, o = threadIdx.x;
    float s0 = 0.f, s1 = 0.f;
    int base = b * NSP + ch * CHS;
#pragma unroll 4
    for (int r = 0; r < CHS; r++) {
        int p = d_perm[base + r];
        float bv = d_bsort[base + r];
        float g = d_gx[((size_t)b * NSP + p) * CI + o];
        s0 += g;
        s1 = fmaf(bv, g, s1);
    }
    d_cs0[(b * NCH + ch) * CI + o] = s0;
    d_cs1[(b * NCH + ch) * CI + o] = s1;
}

__global__ void k_suf2()
{
    int b = blockIdx.x, o = threadIdx.x;
    float a0 = 0.f, a1 = 0.f;
    for (int ch = NCH - 1; ch >= 0; --ch) {
        int i = (b * NCH + ch) * CI + o;
        float t0 = d_cs0[i], t1 = d_cs1[i];
        d_cs0[i] = a0; d_cs1[i] = a1;   // exclusive suffix (chunks strictly after ch)
        a0 += t0; a1 += t1;
    }
    size_t z = ((size_t)b * (NSP + 1) + NSP) * CI + o;
    d_S0[z] = 0.f;
    d_S1[z] = 0.f;
}

__global__ void k_suf3()
{
    int b = blockIdx.y, ch = blockIdx.x, o = threadIdx.x;
    float a0 = d_cs0[(b * NCH + ch) * CI + o];
    float a1 = d_cs1[(b * NCH + ch) * CI + o];
    for (int r = CHS - 1; r >= 0; --r) {
        int rr = ch * CHS + r;
        int p = d_perm[b * NSP + rr];
        float bv = d_bsort[b * NSP + rr];
        float g = d_gx[((size_t)b * NSP + p) * CI + o];
        a0 += g;
        a1 = fmaf(bv, g, a1);
        d_S0[((size_t)b * (NSP + 1) + rr) * CI + o] = a0;
        d_S1[((size_t)b * (NSP + 1) + rr) * CI + o] = a1;
    }
}

// ---------------- binary search: first k with bsort[k] > -t ----------------
__global__ void k_lb()
{
    int i = blockIdx.x * 256 + threadIdx.x;
    if (i >= BB * NSP) return;
    int b = i / NSP;
    float keyv = -d_av[i];
    const float* sb = d_bsort + b * NSP;
    int lo = 0, hi = NSP;
    while (lo < hi) {
        int mid = (lo + hi) >> 1;
        if (__ldg(sb + mid) > keyv) hi = mid; else lo = mid + 1;
    }
    d_lbi[i] = lo;
}

// ---------------- y[b,n,o] = (t*S0[lb] + S1[lb]) / N ----------------
__global__ void k_y()
{
    int b = blockIdx.y;
    int n0 = blockIdx.x * CHS;
    int o = threadIdx.x;
    const float invN = 1.0f / 3136.0f;
#pragma unroll 4
    for (int nn = 0; nn < CHS; nn++) {
        int n = n0 + nn;
        float t = d_av[b * NSP + n];
        int lb = d_lbi[b * NSP + n];
        size_t s = ((size_t)b * (NSP + 1) + lb) * CI + o;
        d_y[((size_t)b * NSP + n) * CI + o] = fmaf(t, d_S0[s], d_S1[s]) * invN;
    }
}

// ---------------- final: out = (wz@y)*inv + obias + x ----------------
__global__ void k_final(const float* __restrict__ wz_w, const float* __restrict__ x,
                        float* __restrict__ out)
{
    __shared__ float wzs[C][33];   // [cc][k], reused as z-staging [cc][nn]
    __shared__ float ys[32][33];   // [k][nn]
    int b = blockIdx.y;
    int n0 = blockIdx.x * 32;
    int tid = threadIdx.x, lane = tid & 31, warp = tid >> 5;
    float acc[8][4];
#pragma unroll
    for (int i = 0; i < 8; i++)
#pragma unroll
        for (int j = 0; j < 4; j++) acc[i][j] = 0.f;

    for (int o0 = 0; o0 < CI; o0 += 32) {
        for (int idx = tid; idx < C * 32; idx += 256) {
            int cc = idx >> 5, k = idx & 31;
            wzs[cc][k] = wz_w[cc * CI + o0 + k];
        }
        for (int idx = tid; idx < 32 * 32; idx += 256) {
            int nn = idx >> 5, k = idx & 31;
            ys[k][nn] = d_y[((size_t)b * NSP + n0 + nn) * CI + o0 + k];
        }
        __syncthreads();
#pragma unroll
        for (int k = 0; k < 32; k++) {
            float yv[4];
#pragma unroll
            for (int j = 0; j < 4; j++) yv[j] = ys[k][warp * 4 + j];
#pragma unroll
            for (int i = 0; i < 8; i++) {
                float w = wzs[lane + 32 * i][k];
#pragma unroll
                for (int j = 0; j < 4; j++) acc[i][j] = fmaf(w, yv[j], acc[i][j]);
            }
        }
        __syncthreads();
    }

    // stage z into wzs (as [cc][nn]) with BN fold applied
#pragma unroll
    for (int i = 0; i < 8; i++) {
        int cc = lane + 32 * i;
        float iv = d_inv[cc], ob = d_obias[cc];
#pragma unroll
        for (int j = 0; j < 4; j++)
            wzs[cc][warp * 4 + j] = fmaf(acc[i][j], iv, ob);
    }
    __syncthreads();

    // coalesced writeback + residual
    for (int r = 0; r < 32; r++) {
        int cc = warp * 32 + r;
        size_t g = ((size_t)b * C + cc) * NSP + n0 + lane;
        out[g] = wzs[cc][lane] + x[g];
    }
}

// ---------------- launch ----------------
extern "C" void kernel_launch(void* const* d_in, const int* in_sizes, int n_in,
                              void* d_out, int out_size)
{
    const float* x       = (const float*)d_in[0];
    const float* g_w     = (const float*)d_in[1];
    const float* g_b     = (const float*)d_in[2];
    const float* theta_w = (const float*)d_in[3];
    const float* theta_b = (const float*)d_in[4];
    const float* phi_w   = (const float*)d_in[5];
    const float* phi_b   = (const float*)d_in[6];
    const float* wf_w    = (const float*)d_in[7];
    const float* wf_b    = (const float*)d_in[8];
    const float* wz_w    = (const float*)d_in[9];
    const float* wz_b    = (const float*)d_in[10];
    const float* bn_g    = (const float*)d_in[11];
    const float* bn_b    = (const float*)d_in[12];
    const float* bn_m    = (const float*)d_in[13];
    const float* bn_v    = (const float*)d_in[14];
    float* out = (float*)d_out;

    k_prep<<<1, 256>>>(theta_w, theta_b, phi_w, phi_b, wf_w, wf_b,
                       wz_b, bn_g, bn_b, bn_m, bn_v);
    k_tr<<<128, 256>>>(g_w);
    k_ab<<<dim3((NSP + 255) / 256, BB), 256>>>(x);
    k_gemm1<<<dim3(NSP / 64, BB), 256>>>(x, g_b);
    k_sort<<<BB, 512>>>();
    k_suf1<<<dim3(NCH, BB), 128>>>();
    k_suf2<<<BB, 128>>>();
    k_suf3<<<dim3(NCH, BB), 128>>>();
    k_lb<<<(BB * NSP + 255) / 256, 256>>>();
    k_y<<<dim3(NCH, BB), 128>>>();
    k_final<<<dim3(NSP / 32, BB), 256>>>(wz_w, x, out);
}

// round 2
// speedup vs baseline: 1.1405x; 1.1405x over previous
#include <cuda_runtime.h>

#define BB   8
#define C    256
#define CI   128
#define NSP  3136
#define NCH  49
#define CHS  64
#define PN   4096
#define NT1  (NSP + 1)

// ---------------- scratch ----------------
__device__ float d_u[C], d_v[C], d_sc[C], d_obias[C], d_mb[C];
__device__ float d_ca, d_cb;
__device__ float d_MT[C * C];                         // [c][cc] = (wz@g_w)^T
__device__ float d_h[(size_t)BB * NSP * C];           // h[b][n][cc]
__device__ float d_av[BB * NSP], d_bvv[BB * NSP];
__device__ float d_bsort[BB * NSP];
__device__ int   d_perm[BB * NSP];
__device__ int   d_lbi[BB * NSP];
__device__ float d_cs0[BB * NCH * C], d_cs1[BB * NCH * C];
__device__ float2 d_T[(size_t)BB * NT1 * C];          // (T0,T1) interleaved

// ---------------- prep: fold everything foldable ----------------
__global__ void k_prep(const float* __restrict__ theta_w, const float* __restrict__ theta_b,
                       const float* __restrict__ phi_w,   const float* __restrict__ phi_b,
                       const float* __restrict__ wf_w,    const float* __restrict__ wf_b,
                       const float* __restrict__ wz_w,    const float* __restrict__ wz_b,
                       const float* __restrict__ g_b,     const float* __restrict__ gamma_,
                       const float* __restrict__ beta_,   const float* __restrict__ mean_,
                       const float* __restrict__ var_)
{
    int c = threadIdx.x;  // 0..255
    float u = 0.f, v = 0.f, mb = 0.f;
    for (int o = 0; o < CI; o++) {
        u  = fmaf(wf_w[o],        theta_w[o * C + c], u);
        v  = fmaf(wf_w[CI + o],   phi_w[o * C + c],   v);
        mb = fmaf(wz_w[c * CI + o], g_b[o],            mb);
    }
    d_u[c] = u; d_v[c] = v; d_mb[c] = mb;
    float iv = gamma_[c] / sqrtf(var_[c] + 1e-5f);
    d_sc[c]    = iv * (1.0f / (float)NSP);
    d_obias[c] = (wz_b[c] - mean_[c]) * iv + beta_[c];
    if (c == 0) {
        float ca = 0.f, cb = 0.f;
        for (int o = 0; o < CI; o++) {
            ca = fmaf(wf_w[o],      theta_b[o], ca);
            cb = fmaf(wf_w[CI + o], phi_b[o],   cb);
        }
        d_ca = ca + wf_b[0];
        d_cb = cb;
    }
}

// ---------------- MT[c][cc] = sum_o wz[cc][o] g_w[o][c] ----------------
__global__ void k_mt(const float* __restrict__ g_w, const float* __restrict__ wz_w)
{
    __shared__ float gcol[4][CI];
    int c0 = blockIdx.x * 4;
    int tid = threadIdx.x;
    for (int i = tid; i < 4 * CI; i += 256) {
        int j = i >> 7, o = i & 127;
        gcol[j][o] = g_w[o * C + c0 + j];
    }
    __syncthreads();
    int cc = tid;
    float a0 = 0.f, a1 = 0.f, a2 = 0.f, a3 = 0.f;
    for (int o = 0; o < CI; o++) {
        float w = wz_w[cc * CI + o];
        a0 = fmaf(w, gcol[0][o], a0);
        a1 = fmaf(w, gcol[1][o], a1);
        a2 = fmaf(w, gcol[2][o], a2);
        a3 = fmaf(w, gcol[3][o], a3);
    }
    d_MT[(c0 + 0) * C + cc] = a0;
    d_MT[(c0 + 1) * C + cc] = a1;
    d_MT[(c0 + 2) * C + cc] = a2;
    d_MT[(c0 + 3) * C + cc] = a3;
}

// ---------------- h-GEMM (+ fused a/b): h[b,n,cc] = M x + mb ----------------
__global__ void __launch_bounds__(256) k_hgemm(const float* __restrict__ x)
{
    __shared__ float mt[16][128];
    __shared__ float xs[16][33];
    __shared__ float us[16], vs[16];
    int half = blockIdx.x;            // cc half: 0 or 1
    int n0   = blockIdx.y * 32;
    int b    = blockIdx.z;
    int tid = threadIdx.x, lane = tid & 31, warp = tid >> 5;
    float acc[4][4];
#pragma unroll
    for (int j = 0; j < 4; j++)
#pragma unroll
        for (int i = 0; i < 4; i++) acc[j][i] = 0.f;
    float aab = 0.f, bab = 0.f;

    for (int c0 = 0; c0 < C; c0 += 16) {
        for (int i = tid; i < 16 * 128; i += 256) {
            int k = i >> 7, ccl = i & 127;
            mt[k][ccl] = d_MT[(c0 + k) * C + half * 128 + ccl];
        }
        for (int i = tid; i < 16 * 32; i += 256) {
            int k = i >> 5, nn = i & 31;
            xs[k][nn] = x[((size_t)(b * C + c0 + k)) * NSP + n0 + nn];
        }
        if (tid < 16) us[tid] = d_u[c0 + tid];
        else if (tid < 32) vs[tid - 16] = d_v[c0 + tid - 16];
        __syncthreads();
#pragma unroll
        for (int k = 0; k < 16; k++) {
            float4 m4 = *reinterpret_cast<const float4*>(&mt[k][lane * 4]);
#pragma unroll
            for (int j = 0; j < 4; j++) {
                float xv = xs[k][warp * 4 + j];
                acc[j][0] = fmaf(m4.x, xv, acc[j][0]);
                acc[j][1] = fmaf(m4.y, xv, acc[j][1]);
                acc[j][2] = fmaf(m4.z, xv, acc[j][2]);
                acc[j][3] = fmaf(m4.w, xv, acc[j][3]);
            }
        }
        if (half == 0 && tid < 32) {
#pragma unroll
            for (int k = 0; k < 16; k++) {
                float xv = xs[k][tid];
                aab = fmaf(us[k], xv, aab);
                bab = fmaf(vs[k], xv, bab);
            }
        }
        __syncthreads();
    }
    float4 mb4 = *reinterpret_cast<const float4*>(&d_mb[half * 128 + lane * 4]);
#pragma unroll
    for (int j = 0; j < 4; j++) {
        int n = n0 + warp * 4 + j;
        float4 r = make_float4(acc[j][0] + mb4.x, acc[j][1] + mb4.y,
                               acc[j][2] + mb4.z, acc[j][3] + mb4.w);
        *reinterpret_cast<float4*>(&d_h[((size_t)b * NSP + n) * C + half * 128 + lane * 4]) = r;
    }
    if (half == 0 && tid < 32) {
        d_av[b * NSP + n0 + tid]  = aab + d_ca;
        d_bvv[b * NSP + n0 + tid] = bab + d_cb;
    }
}

// ---------------- sort b per batch (bitonic, 4096 pad) ----------------
__global__ void k_sort()
{
    __shared__ float key[PN];
    __shared__ int   idx[PN];
    int b = blockIdx.x;
    for (int e = threadIdx.x; e < PN; e += blockDim.x) {
        key[e] = (e < NSP) ? d_bvv[b * NSP + e] : 3.4e38f;
        idx[e] = e;
    }
    __syncthreads();
    for (int k = 2; k <= PN; k <<= 1) {
        for (int j = k >> 1; j > 0; j >>= 1) {
            for (int e = threadIdx.x; e < PN; e += blockDim.x) {
                int ixj = e ^ j;
                if (ixj > e) {
                    bool up = ((e & k) == 0);
                    float ka = key[e], kb = key[ixj];
                    if (up ? (ka > kb) : (ka < kb)) {
                        key[e] = kb; key[ixj] = ka;
                        int t = idx[e]; idx[e] = idx[ixj]; idx[ixj] = t;
                    }
                }
            }
            __syncthreads();
        }
    }
    for (int e = threadIdx.x; e < NSP; e += blockDim.x) {
        d_bsort[b * NSP + e] = key[e];
        d_perm[b * NSP + e]  = idx[e];
    }
}

// ---------------- chunk totals ----------------
__global__ void k_suf1()
{
    __shared__ int sp[CHS];
    __shared__ float sb[CHS];
    int b = blockIdx.y, ch = blockIdx.x, cc = threadIdx.x;
    int base = b * NSP + ch * CHS;
    if (cc < CHS) { sp[cc] = d_perm[base + cc]; sb[cc] = d_bsort[base + cc]; }
    __syncthreads();
    float s0 = 0.f, s1 = 0.f;
#pragma unroll 4
    for (int r = 0; r < CHS; r++) {
        float g = d_h[((size_t)b * NSP + sp[r]) * C + cc];
        s0 += g;
        s1 = fmaf(sb[r], g, s1);
    }
    d_cs0[(b * NCH + ch) * C + cc] = s0;
    d_cs1[(b * NCH + ch) * C + cc] = s1;
}

// ---------------- exclusive chunk suffix ----------------
__global__ void k_suf2()
{
    int b = blockIdx.x, cc = threadIdx.x;
    float a0 = 0.f, a1 = 0.f;
    for (int ch = NCH - 1; ch >= 0; --ch) {
        int i = (b * NCH + ch) * C + cc;
        float t0 = d_cs0[i], t1 = d_cs1[i];
        d_cs0[i] = a0; d_cs1[i] = a1;
        a0 += t0; a1 += t1;
    }
    d_T[((size_t)b * NT1 + NSP) * C + cc] = make_float2(0.f, 0.f);
}

// ---------------- full suffix arrays (interleaved T0,T1) ----------------
__global__ void k_suf3()
{
    __shared__ int sp[CHS];
    __shared__ float sb[CHS];
    int b = blockIdx.y, ch = blockIdx.x, cc = threadIdx.x;
    int base = b * NSP + ch * CHS;
    if (cc < CHS) { sp[cc] = d_perm[base + cc]; sb[cc] = d_bsort[base + cc]; }
    __syncthreads();
    float a0 = d_cs0[(b * NCH + ch) * C + cc];
    float a1 = d_cs1[(b * NCH + ch) * C + cc];
    for (int r = CHS - 1; r >= 0; --r) {
        int rr = ch * CHS + r;
        float g = d_h[((size_t)b * NSP + sp[r]) * C + cc];
        a0 += g;
        a1 = fmaf(sb[r], g, a1);
        d_T[((size_t)b * NT1 + rr) * C + cc] = make_float2(a0, a1);
    }
}

// ---------------- binary search ----------------
__global__ void k_lb()
{
    int i = blockIdx.x * 256 + threadIdx.x;
    if (i >= BB * NSP) return;
    int b = i / NSP;
    float keyv = -d_av[i];
    const float* sb = d_bsort + b * NSP;
    int lo = 0, hi = NSP;
    while (lo < hi) {
        int mid = (lo + hi) >> 1;
        if (__ldg(sb + mid) > keyv) hi = mid; else lo = mid + 1;
    }
    d_lbi[i] = lo;
}

// ---------------- output: gather T rows, fold BN, add residual ----------------
__global__ void __launch_bounds__(256) k_out(const float* __restrict__ x,
                                             float* __restrict__ out)
{
    __shared__ float zt[C][33];
    __shared__ float tl[32];
    __shared__ int lbl[32];
    int b = blockIdx.y, n0 = blockIdx.x * 32;
    int tid = threadIdx.x, lane = tid & 31, warp = tid >> 5;
    if (tid < 32) {
        tl[tid]  = d_av[b * NSP + n0 + tid];
        lbl[tid] = d_lbi[b * NSP + n0 + tid];
    }
    __syncthreads();
#pragma unroll
    for (int s = 0; s < 4; s++) {
        int nn = warp + s * 8;
        float t = tl[nn];
        size_t base = ((size_t)b * NT1 + lbl[nn]) * C;
#pragma unroll
        for (int it = 0; it < 8; it++) {
            int cc = it * 32 + lane;
            float2 T = d_T[base + cc];
            zt[cc][nn] = fmaf(fmaf(t, T.x, T.y), d_sc[cc], d_obias[cc]);
        }
    }
    __syncthreads();
#pragma unroll 4
    for (int r = 0; r < 32; r++) {
        int cc = warp * 32 + r;
        size_t g = ((size_t)(b * C + cc)) * NSP + n0 + lane;
        out[g] = zt[cc][lane] + x[g];
    }
}

// ---------------- launch ----------------
extern "C" void kernel_launch(void* const* d_in, const int* in_sizes, int n_in,
                              void* d_out, int out_size)
{
    const float* x       = (const float*)d_in[0];
    const float* g_w     = (const float*)d_in[1];
    const float* g_b     = (const float*)d_in[2];
    const float* theta_w = (const float*)d_in[3];
    const float* theta_b = (const float*)d_in[4];
    const float* phi_w   = (const float*)d_in[5];
    const float* phi_b   = (const float*)d_in[6];
    const float* wf_w    = (const float*)d_in[7];
    const float* wf_b    = (const float*)d_in[8];
    const float* wz_w    = (const float*)d_in[9];
    const float* wz_b    = (const float*)d_in[10];
    const float* bn_g    = (const float*)d_in[11];
    const float* bn_b    = (const float*)d_in[12];
    const float* bn_m    = (const float*)d_in[13];
    const float* bn_v    = (const float*)d_in[14];
    float* out = (float*)d_out;

    k_prep<<<1, 256>>>(theta_w, theta_b, phi_w, phi_b, wf_w, wf_b,
                       wz_w, wz_b, g_b, bn_g, bn_b, bn_m, bn_v);
    k_mt<<<64, 256>>>(g_w, wz_w);
    k_hgemm<<<dim3(2, NSP / 32, BB), 256>>>(x);
    k_sort<<<BB, 1024>>>();
    k_lb<<<(BB * NSP + 255) / 256, 256>>>();
    k_suf1<<<dim3(NCH, BB), 256>>>();
    k_suf2<<<BB, 256>>>();
    k_suf3<<<dim3(NCH, BB), 256>>>();
    k_out<<<dim3(NSP / 32, BB), 256>>>(x, out);
}

// round 3
// speedup vs baseline: 1.3785x; 1.2087x over previous
#include <cuda_runtime.h>

#define BB   8
#define C    256
#define CI   128
#define NSP  3136
#define NCH  49
#define CHS  64
#define PN   4096
#define NT1  (NSP + 1)

// ---------------- f32x2 helpers ----------------
__device__ __forceinline__ unsigned long long fma2(unsigned long long a,
                                                   unsigned long long b,
                                                   unsigned long long c)
{
    unsigned long long d;
    asm("fma.rn.f32x2 %0, %1, %2, %3;" : "=l"(d) : "l"(a), "l"(b), "l"(c));
    return d;
}
__device__ __forceinline__ unsigned long long add2(unsigned long long a,
                                                   unsigned long long b)
{
    unsigned long long d;
    asm("add.rn.f32x2 %0, %1, %2;" : "=l"(d) : "l"(a), "l"(b));
    return d;
}
__device__ __forceinline__ unsigned long long bcast2(float x)
{
    unsigned long long d;
    asm("mov.b64 %0, {%1, %1};" : "=l"(d) : "r"(__float_as_uint(x)));
    return d;
}

// ---------------- scratch ----------------
__device__ float d_u[C], d_v[C], d_sc[C], d_obias[C], d_mb[C];
__device__ float d_ca, d_cb;
__device__ float d_MT[C * C];                         // [c][cc] = (wz@g_w)^T
__device__ float d_h[(size_t)BB * NSP * C];           // h[b][n][cc]
__device__ float d_av[BB * NSP], d_bvv[BB * NSP];
__device__ float d_bsort[BB * NSP];
__device__ int   d_perm[BB * NSP];
__device__ int   d_lbi[BB * NSP];
__device__ float d_cs0[BB * NCH * C], d_cs1[BB * NCH * C];
__device__ float2 d_T[(size_t)BB * NT1 * C];          // (T0,T1) interleaved

// ---------------- prep ----------------
__global__ void k_prep(const float* __restrict__ theta_w, const float* __restrict__ theta_b,
                       const float* __restrict__ phi_w,   const float* __restrict__ phi_b,
                       const float* __restrict__ wf_w,    const float* __restrict__ wf_b,
                       const float* __restrict__ wz_w,    const float* __restrict__ wz_b,
                       const float* __restrict__ g_b,     const float* __restrict__ gamma_,
                       const float* __restrict__ beta_,   const float* __restrict__ mean_,
                       const float* __restrict__ var_)
{
    int c = threadIdx.x;  // 0..255
    float u = 0.f, v = 0.f, mb = 0.f;
    for (int o = 0; o < CI; o++) {
        u  = fmaf(wf_w[o],          theta_w[o * C + c], u);
        v  = fmaf(wf_w[CI + o],     phi_w[o * C + c],   v);
        mb = fmaf(wz_w[c * CI + o], g_b[o],              mb);
    }
    d_u[c] = u; d_v[c] = v; d_mb[c] = mb;
    float iv = gamma_[c] / sqrtf(var_[c] + 1e-5f);
    d_sc[c]    = iv * (1.0f / (float)NSP);
    d_obias[c] = (wz_b[c] - mean_[c]) * iv + beta_[c];
    if (c == 0) {
        float ca = 0.f, cb = 0.f;
        for (int o = 0; o < CI; o++) {
            ca = fmaf(wf_w[o],      theta_b[o], ca);
            cb = fmaf(wf_w[CI + o], phi_b[o],   cb);
        }
        d_ca = ca + wf_b[0];
        d_cb = cb;
    }
}

// ---------------- MT[c][cc] = sum_o wz[cc][o] g_w[o][c] ----------------
__global__ void k_mt(const float* __restrict__ g_w, const float* __restrict__ wz_w)
{
    __shared__ float gcol[4][CI];
    int c0 = blockIdx.x * 4;
    int tid = threadIdx.x;
    for (int i = tid; i < 4 * CI; i += 256) {
        int j = i >> 7, o = i & 127;
        gcol[j][o] = g_w[o * C + c0 + j];
    }
    __syncthreads();
    int cc = tid;
    float a0 = 0.f, a1 = 0.f, a2 = 0.f, a3 = 0.f;
    for (int o = 0; o < CI; o++) {
        float w = wz_w[cc * CI + o];
        a0 = fmaf(w, gcol[0][o], a0);
        a1 = fmaf(w, gcol[1][o], a1);
        a2 = fmaf(w, gcol[2][o], a2);
        a3 = fmaf(w, gcol[3][o], a3);
    }
    d_MT[(c0 + 0) * C + cc] = a0;
    d_MT[(c0 + 1) * C + cc] = a1;
    d_MT[(c0 + 2) * C + cc] = a2;
    d_MT[(c0 + 3) * C + cc] = a3;
}

// ---------------- h-GEMM with f32x2: h[b,n,cc] = M x + mb (+ fused a/b) ----------------
__global__ void __launch_bounds__(256) k_hgemm(const float* __restrict__ x)
{
    __shared__ __align__(16) float mt[16][128];
    __shared__ __align__(16) float xs[16][64];
    __shared__ float us[16], vs[16];
    int half = blockIdx.x;            // cc half: 0 or 1
    int n0   = blockIdx.y * 64;
    int b    = blockIdx.z;
    int tid = threadIdx.x, lane = tid & 31, warp = tid >> 5;
    int wc = warp & 3, wn = warp >> 2;
    int lc = lane & 3, ln = lane >> 2;
    int ccb = wc * 32 + lc * 8;       // 8 cc per thread (4 pairs)
    int nb  = wn * 32 + ln * 4;       // 4 n per thread

    unsigned long long acc[4][4];
#pragma unroll
    for (int p = 0; p < 4; p++)
#pragma unroll
        for (int j = 0; j < 4; j++) acc[p][j] = 0ull;
    float aab = 0.f, bab = 0.f;

    // global load indices
    int mk = tid >> 5, mo = (tid & 31) * 4;          // mt: 16x128, 2 float4 per thread
    int xk = tid >> 4, xn = (tid & 15) * 4;          // xs: 16x64, 1 float4 per thread

    for (int c0 = 0; c0 < C; c0 += 16) {
        *reinterpret_cast<float4*>(&mt[mk][mo]) =
            *reinterpret_cast<const float4*>(&d_MT[(c0 + mk) * C + half * 128 + mo]);
        *reinterpret_cast<float4*>(&mt[mk + 8][mo]) =
            *reinterpret_cast<const float4*>(&d_MT[(c0 + mk + 8) * C + half * 128 + mo]);
        *reinterpret_cast<float4*>(&xs[xk][xn]) =
            *reinterpret_cast<const float4*>(&x[((size_t)(b * C + c0 + xk)) * NSP + n0 + xn]);
        if (tid < 16) us[tid] = d_u[c0 + tid];
        else if (tid < 32) vs[tid - 16] = d_v[c0 + tid - 16];
        __syncthreads();
#pragma unroll
        for (int k = 0; k < 16; k++) {
            ulonglong2 m01 = *reinterpret_cast<const ulonglong2*>(&mt[k][ccb]);
            ulonglong2 m23 = *reinterpret_cast<const ulonglong2*>(&mt[k][ccb + 4]);
            float4 xv = *reinterpret_cast<const float4*>(&xs[k][nb]);
            unsigned long long xb0 = bcast2(xv.x), xb1 = bcast2(xv.y);
            unsigned long long xb2 = bcast2(xv.z), xb3 = bcast2(xv.w);
            acc[0][0] = fma2(m01.x, xb0, acc[0][0]);
            acc[1][0] = fma2(m01.y, xb0, acc[1][0]);
            acc[2][0] = fma2(m23.x, xb0, acc[2][0]);
            acc[3][0] = fma2(m23.y, xb0, acc[3][0]);
            acc[0][1] = fma2(m01.x, xb1, acc[0][1]);
            acc[1][1] = fma2(m01.y, xb1, acc[1][1]);
            acc[2][1] = fma2(m23.x, xb1, acc[2][1]);
            acc[3][1] = fma2(m23.y, xb1, acc[3][1]);
            acc[0][2] = fma2(m01.x, xb2, acc[0][2]);
            acc[1][2] = fma2(m01.y, xb2, acc[1][2]);
            acc[2][2] = fma2(m23.x, xb2, acc[2][2]);
            acc[3][2] = fma2(m23.y, xb2, acc[3][2]);
            acc[0][3] = fma2(m01.x, xb3, acc[0][3]);
            acc[1][3] = fma2(m01.y, xb3, acc[1][3]);
            acc[2][3] = fma2(m23.x, xb3, acc[2][3]);
            acc[3][3] = fma2(m23.y, xb3, acc[3][3]);
        }
        if (half == 0 && tid < 64) {
#pragma unroll
            for (int k = 0; k < 16; k++) {
                float xv = xs[k][tid];
                aab = fmaf(us[k], xv, aab);
                bab = fmaf(vs[k], xv, bab);
            }
        }
        __syncthreads();
    }

    ulonglong2 mb01 = *reinterpret_cast<const ulonglong2*>(&d_mb[half * 128 + ccb]);
    ulonglong2 mb23 = *reinterpret_cast<const ulonglong2*>(&d_mb[half * 128 + ccb + 4]);
#pragma unroll
    for (int j = 0; j < 4; j++) {
        int n = n0 + nb + j;
        float* hp = &d_h[((size_t)b * NSP + n) * C + half * 128 + ccb];
        ulonglong2 r0 = make_ulonglong2(add2(acc[0][j], mb01.x), add2(acc[1][j], mb01.y));
        ulonglong2 r1 = make_ulonglong2(add2(acc[2][j], mb23.x), add2(acc[3][j], mb23.y));
        *reinterpret_cast<ulonglong2*>(hp)     = r0;
        *reinterpret_cast<ulonglong2*>(hp + 4) = r1;
    }
    if (half == 0 && tid < 64) {
        d_av[b * NSP + n0 + tid]  = aab + d_ca;
        d_bvv[b * NSP + n0 + tid] = bab + d_cb;
    }
}

// ---------------- sort: packed u64 (key|idx) bitonic ----------------
__global__ void k_sort()
{
    __shared__ unsigned long long s[PN];
    int b = blockIdx.x;
    int tid = threadIdx.x;
    for (int e = tid; e < PN; e += 1024) {
        unsigned int u;
        if (e < NSP) {
            unsigned int raw = __float_as_uint(d_bvv[b * NSP + e]);
            u = ((int)raw < 0) ? ~raw : (raw | 0x80000000u);
        } else u = 0xFFFFFFFFu;
        s[e] = ((unsigned long long)u << 32) | (unsigned int)e;
    }
    __syncthreads();
    for (int k = 2; k <= PN; k <<= 1) {
        for (int j = k >> 1; j > 0; j >>= 1) {
#pragma unroll 4
            for (int e = tid; e < PN; e += 1024) {
                int ixj = e ^ j;
                if (ixj > e) {
                    bool up = ((e & k) == 0);
                    unsigned long long va = s[e], vb = s[ixj];
                    if (up ? (va > vb) : (va < vb)) {
                        s[e] = vb; s[ixj] = va;
                    }
                }
            }
            __syncthreads();
        }
    }
    for (int e = tid; e < NSP; e += 1024) {
        unsigned long long v = s[e];
        unsigned int hi = (unsigned int)(v >> 32);
        unsigned int raw = (hi & 0x80000000u) ? (hi ^ 0x80000000u) : ~hi;
        d_bsort[b * NSP + e] = __uint_as_float(raw);
        d_perm[b * NSP + e]  = (int)(v & 0xFFFFFFFFu);
    }
}

// ---------------- chunk totals ----------------
__global__ void k_suf1()
{
    __shared__ int sp[CHS];
    __shared__ float sb[CHS];
    int b = blockIdx.y, ch = blockIdx.x, cc = threadIdx.x;
    int base = b * NSP + ch * CHS;
    if (cc < CHS) { sp[cc] = d_perm[base + cc]; sb[cc] = d_bsort[base + cc]; }
    __syncthreads();
    float s0 = 0.f, s1 = 0.f;
#pragma unroll 4
    for (int r = 0; r < CHS; r++) {
        float g = d_h[((size_t)b * NSP + sp[r]) * C + cc];
        s0 += g;
        s1 = fmaf(sb[r], g, s1);
    }
    d_cs0[(b * NCH + ch) * C + cc] = s0;
    d_cs1[(b * NCH + ch) * C + cc] = s1;
}

// ---------------- exclusive chunk suffix ----------------
__global__ void k_suf2()
{
    int b = blockIdx.x, cc = threadIdx.x;
    float a0 = 0.f, a1 = 0.f;
    for (int ch = NCH - 1; ch >= 0; --ch) {
        int i = (b * NCH + ch) * C + cc;
        float t0 = d_cs0[i], t1 = d_cs1[i];
        d_cs0[i] = a0; d_cs1[i] = a1;
        a0 += t0; a1 += t1;
    }
    d_T[((size_t)b * NT1 + NSP) * C + cc] = make_float2(0.f, 0.f);
}

// ---------------- full suffix arrays ----------------
__global__ void k_suf3()
{
    __shared__ int sp[CHS];
    __shared__ float sb[CHS];
    int b = blockIdx.y, ch = blockIdx.x, cc = threadIdx.x;
    int base = b * NSP + ch * CHS;
    if (cc < CHS) { sp[cc] = d_perm[base + cc]; sb[cc] = d_bsort[base + cc]; }
    __syncthreads();
    float a0 = d_cs0[(b * NCH + ch) * C + cc];
    float a1 = d_cs1[(b * NCH + ch) * C + cc];
    for (int r = CHS - 1; r >= 0; --r) {
        int rr = ch * CHS + r;
        float g = d_h[((size_t)b * NSP + sp[r]) * C + cc];
        a0 += g;
        a1 = fmaf(sb[r], g, a1);
        d_T[((size_t)b * NT1 + rr) * C + cc] = make_float2(a0, a1);
    }
}

// ---------------- binary search ----------------
__global__ void k_lb()
{
    int i = blockIdx.x * 256 + threadIdx.x;
    if (i >= BB * NSP) return;
    int b = i / NSP;
    float keyv = -d_av[i];
    const float* sb = d_bsort + b * NSP;
    int lo = 0, hi = NSP;
    while (lo < hi) {
        int mid = (lo + hi) >> 1;
        if (__ldg(sb + mid) > keyv) hi = mid; else lo = mid + 1;
    }
    d_lbi[i] = lo;
}

// ---------------- output ----------------
__global__ void __launch_bounds__(256) k_out(const float* __restrict__ x,
                                             float* __restrict__ out)
{
    __shared__ float zt[C][33];
    __shared__ float tl[32];
    __shared__ int lbl[32];
    int b = blockIdx.y, n0 = blockIdx.x * 32;
    int tid = threadIdx.x, lane = tid & 31, warp = tid >> 5;
    if (tid < 32) {
        tl[tid]  = d_av[b * NSP + n0 + tid];
        lbl[tid] = d_lbi[b * NSP + n0 + tid];
    }
    __syncthreads();
#pragma unroll
    for (int s = 0; s < 4; s++) {
        int nn = warp + s * 8;
        float t = tl[nn];
        size_t base = ((size_t)b * NT1 + lbl[nn]) * C;
#pragma unroll
        for (int it = 0; it < 8; it++) {
            int cc = it * 32 + lane;
            float2 T = d_T[base + cc];
            zt[cc][nn] = fmaf(fmaf(t, T.x, T.y), d_sc[cc], d_obias[cc]);
        }
    }
    __syncthreads();
#pragma unroll 4
    for (int r = 0; r < 32; r++) {
        int cc = warp * 32 + r;
        size_t g = ((size_t)(b * C + cc)) * NSP + n0 + lane;
        out[g] = zt[cc][lane] + x[g];
    }
}

// ---------------- launch ----------------
extern "C" void kernel_launch(void* const* d_in, const int* in_sizes, int n_in,
                              void* d_out, int out_size)
{
    const float* x       = (const float*)d_in[0];
    const float* g_w     = (const float*)d_in[1];
    const float* g_b     = (const float*)d_in[2];
    const float* theta_w = (const float*)d_in[3];
    const float* theta_b = (const float*)d_in[4];
    const float* phi_w   = (const float*)d_in[5];
    const float* phi_b   = (const float*)d_in[6];
    const float* wf_w    = (const float*)d_in[7];
    const float* wf_b    = (const float*)d_in[8];
    const float* wz_w    = (const float*)d_in[9];
    const float* wz_b    = (const float*)d_in[10];
    const float* bn_g    = (const float*)d_in[11];
    const float* bn_b    = (const float*)d_in[12];
    const float* bn_m    = (const float*)d_in[13];
    const float* bn_v    = (const float*)d_in[14];
    float* out = (float*)d_out;

    k_prep<<<1, 256>>>(theta_w, theta_b, phi_w, phi_b, wf_w, wf_b,
                       wz_w, wz_b, g_b, bn_g, bn_b, bn_m, bn_v);
    k_mt<<<64, 256>>>(g_w, wz_w);
    k_hgemm<<<dim3(2, NSP / 64, BB), 256>>>(x);
    k_sort<<<BB, 1024>>>();
    k_lb<<<(BB * NSP + 255) / 256, 256>>>();
    k_suf1<<<dim3(NCH, BB), 256>>>();
    k_suf2<<<BB, 256>>>();
    k_suf3<<<dim3(NCH, BB), 256>>>();
    k_out<<<dim3(NSP / 32, BB), 256>>>(x, out);
}

// round 4
// speedup vs baseline: 1.5122x; 1.0969x over previous
#include <cuda_runtime.h>

#define BB   8
#define C    256
#define CI   128
#define NSP  3136
#define NCH  49
#define CHS  64
#define PN   4096
#define NT1  (NSP + 1)
#define GEMM_BLOCKS (2 * (NSP / 64) * BB)

typedef unsigned long long u64;

// ---------------- f32x2 helpers ----------------
__device__ __forceinline__ u64 fma2(u64 a, u64 b, u64 c)
{
    u64 d;
    asm("fma.rn.f32x2 %0, %1, %2, %3;" : "=l"(d) : "l"(a), "l"(b), "l"(c));
    return d;
}
__device__ __forceinline__ u64 add2(u64 a, u64 b)
{
    u64 d;
    asm("add.rn.f32x2 %0, %1, %2;" : "=l"(d) : "l"(a), "l"(b));
    return d;
}
__device__ __forceinline__ u64 bcast2(float x)
{
    u64 d;
    asm("mov.b64 %0, {%1, %1};" : "=l"(d) : "r"(__float_as_uint(x)));
    return d;
}

// ---------------- scratch ----------------
__device__ float d_u[C], d_v[C], d_sc[C], d_obias[C], d_mb[C];
__device__ float d_ca, d_cb;
__device__ float d_MT[C * C];
__device__ float d_h[(size_t)BB * NSP * C];
__device__ float d_av[BB * NSP];
__device__ u64   d_skey[BB * NSP];
__device__ float d_bsort[BB * NSP];
__device__ int   d_perm[BB * NSP];
__device__ int   d_lbi[BB * NSP];
__device__ float d_cs0[BB * NCH * C], d_cs1[BB * NCH * C];
__device__ float2 d_T[(size_t)BB * NT1 * C];

// ---------------- prep ----------------
__global__ void k_prep(const float* __restrict__ theta_w, const float* __restrict__ theta_b,
                       const float* __restrict__ phi_w,   const float* __restrict__ phi_b,
                       const float* __restrict__ wf_w,    const float* __restrict__ wf_b,
                       const float* __restrict__ wz_w,    const float* __restrict__ wz_b,
                       const float* __restrict__ g_b,     const float* __restrict__ gamma_,
                       const float* __restrict__ beta_,   const float* __restrict__ mean_,
                       const float* __restrict__ var_)
{
    int c = threadIdx.x;
    float u = 0.f, v = 0.f, mb = 0.f;
    for (int o = 0; o < CI; o++) {
        u  = fmaf(wf_w[o],          theta_w[o * C + c], u);
        v  = fmaf(wf_w[CI + o],     phi_w[o * C + c],   v);
        mb = fmaf(wz_w[c * CI + o], g_b[o],              mb);
    }
    d_u[c] = u; d_v[c] = v; d_mb[c] = mb;
    float iv = gamma_[c] / sqrtf(var_[c] + 1e-5f);
    d_sc[c]    = iv * (1.0f / (float)NSP);
    d_obias[c] = (wz_b[c] - mean_[c]) * iv + beta_[c];
    if (c == 0) {
        float ca = 0.f, cb = 0.f;
        for (int o = 0; o < CI; o++) {
            ca = fmaf(wf_w[o],      theta_b[o], ca);
            cb = fmaf(wf_w[CI + o], phi_b[o],   cb);
        }
        d_ca = ca + wf_b[0];
        d_cb = cb;
    }
}

// ---------------- MT = (wz @ g_w)^T ----------------
__global__ void k_mt(const float* __restrict__ g_w, const float* __restrict__ wz_w)
{
    __shared__ float gcol[4][CI];
    int c0 = blockIdx.x * 4;
    int tid = threadIdx.x;
    for (int i = tid; i < 4 * CI; i += 256) {
        int j = i >> 7, o = i & 127;
        gcol[j][o] = g_w[o * C + c0 + j];
    }
    __syncthreads();
    int cc = tid;
    float a0 = 0.f, a1 = 0.f, a2 = 0.f, a3 = 0.f;
    for (int o = 0; o < CI; o++) {
        float w = wz_w[cc * CI + o];
        a0 = fmaf(w, gcol[0][o], a0);
        a1 = fmaf(w, gcol[1][o], a1);
        a2 = fmaf(w, gcol[2][o], a2);
        a3 = fmaf(w, gcol[3][o], a3);
    }
    d_MT[(c0 + 0) * C + cc] = a0;
    d_MT[(c0 + 1) * C + cc] = a1;
    d_MT[(c0 + 2) * C + cc] = a2;
    d_MT[(c0 + 3) * C + cc] = a3;
}

// ---------------- a/b + sort keys ----------------
__global__ void k_ab(const float* __restrict__ x)
{
    int b = blockIdx.y;
    int n = blockIdx.x * 256 + threadIdx.x;
    if (n >= NSP) return;
    const float* xp = x + (size_t)b * C * NSP + n;
    float a = d_ca, bb = d_cb;
#pragma unroll 8
    for (int c = 0; c < C; c++) {
        float xv = xp[(size_t)c * NSP];
        a  = fmaf(d_u[c], xv, a);
        bb = fmaf(d_v[c], xv, bb);
    }
    d_av[b * NSP + n] = a;
    unsigned int raw = __float_as_uint(bb);
    unsigned int key = ((int)raw < 0) ? ~raw : (raw | 0x80000000u);
    d_skey[b * NSP + n] = ((u64)key << 32) | (unsigned int)n;
}

// ---------------- unified: blocks 0..7 sort, rest h-GEMM ----------------
__device__ __forceinline__ void cswap(u64& a, u64& b, bool up)
{
    if ((a > b) == up) { u64 t = a; a = b; b = t; }
}

__global__ void __launch_bounds__(256) k_uni(const float* __restrict__ x)
{
    __shared__ __align__(16) u64 sbuf[PN];   // 32KB; gemm aliases into it
    int bid = blockIdx.x;
    int tid = threadIdx.x;

    if (bid < BB) {
        // ================= SORT PATH =================
        int b = bid;
        for (int e = tid; e < PN; e += 256)
            sbuf[e] = (e < NSP) ? d_skey[b * NSP + e]
                                : ((u64)0xFFFFFFFFu << 32) | (unsigned int)e;
        __syncthreads();

        // initial: fully sort each 8-window (phases k=2,4,8)
        for (int w = tid; w < PN / 8; w += 256) {
            u64 r[8];
#pragma unroll
            for (int i = 0; i < 8; i++) r[i] = sbuf[w * 8 + i];
            // k=2
            cswap(r[0], r[1], true);  cswap(r[2], r[3], false);
            cswap(r[4], r[5], true);  cswap(r[6], r[7], false);
            // k=4, j=2
            cswap(r[0], r[2], true);  cswap(r[1], r[3], true);
            cswap(r[4], r[6], false); cswap(r[5], r[7], false);
            // k=4, j=1
            cswap(r[0], r[1], true);  cswap(r[2], r[3], true);
            cswap(r[4], r[5], false); cswap(r[6], r[7], false);
            // k=8
            bool up8 = ((w & 1) == 0);
            cswap(r[0], r[4], up8); cswap(r[1], r[5], up8);
            cswap(r[2], r[6], up8); cswap(r[3], r[7], up8);
            cswap(r[0], r[2], up8); cswap(r[1], r[3], up8);
            cswap(r[4], r[6], up8); cswap(r[5], r[7], up8);
            cswap(r[0], r[1], up8); cswap(r[2], r[3], up8);
            cswap(r[4], r[5], up8); cswap(r[6], r[7], up8);
#pragma unroll
            for (int i = 0; i < 8; i++) sbuf[w * 8 + i] = r[i];
        }
        __syncthreads();

        for (int k = 16; k <= PN; k <<= 1) {
            for (int j = k >> 1; j >= 8; j >>= 1) {
#pragma unroll 4
                for (int t = tid; t < PN / 2; t += 256) {
                    int e  = ((t & ~(j - 1)) << 1) | (t & (j - 1));
                    int e2 = e + j;
                    bool up = ((e & k) == 0);
                    u64 a = sbuf[e], bq = sbuf[e2];
                    if ((a > bq) == up) { sbuf[e] = bq; sbuf[e2] = a; }
                }
                __syncthreads();
            }
            // local merge j=4,2,1 (direction uniform per 8-window)
            for (int w = tid; w < PN / 8; w += 256) {
                bool up = (((w * 8) & k) == 0);
                u64 r[8];
#pragma unroll
                for (int i = 0; i < 8; i++) r[i] = sbuf[w * 8 + i];
                cswap(r[0], r[4], up); cswap(r[1], r[5], up);
                cswap(r[2], r[6], up); cswap(r[3], r[7], up);
                cswap(r[0], r[2], up); cswap(r[1], r[3], up);
                cswap(r[4], r[6], up); cswap(r[5], r[7], up);
                cswap(r[0], r[1], up); cswap(r[2], r[3], up);
                cswap(r[4], r[5], up); cswap(r[6], r[7], up);
#pragma unroll
                for (int i = 0; i < 8; i++) sbuf[w * 8 + i] = r[i];
            }
            __syncthreads();
        }

        for (int e = tid; e < NSP; e += 256) {
            u64 v = sbuf[e];
            unsigned int hi = (unsigned int)(v >> 32);
            unsigned int raw = (hi & 0x80000000u) ? (hi ^ 0x80000000u) : ~hi;
            d_bsort[b * NSP + e] = __uint_as_float(raw);
            d_perm[b * NSP + e]  = (int)(v & 0xFFFFFFFFu);
        }
        return;
    }

    // ================= GEMM PATH =================
    float (*mt)[128] = reinterpret_cast<float(*)[128]>(sbuf);          // 8KB
    float (*xs)[64]  = reinterpret_cast<float(*)[64]>(sbuf + 1024);    // 4KB @ +8KB

    int g    = bid - BB;
    int half = g & 1;
    int rest = g >> 1;
    int n0   = (rest % (NSP / 64)) * 64;
    int b    = rest / (NSP / 64);
    int lane = tid & 31, warp = tid >> 5;
    int wc = warp & 3, wn = warp >> 2;
    int lc = lane & 3, ln = lane >> 2;
    int ccb = wc * 32 + lc * 8;
    int nb  = wn * 32 + ln * 4;

    u64 acc[4][4];
#pragma unroll
    for (int p = 0; p < 4; p++)
#pragma unroll
        for (int j = 0; j < 4; j++) acc[p][j] = 0ull;

    int mk = tid >> 5, mo = (tid & 31) * 4;
    int xk = tid >> 4, xn = (tid & 15) * 4;

    for (int c0 = 0; c0 < C; c0 += 16) {
        *reinterpret_cast<float4*>(&mt[mk][mo]) =
            *reinterpret_cast<const float4*>(&d_MT[(c0 + mk) * C + half * 128 + mo]);
        *reinterpret_cast<float4*>(&mt[mk + 8][mo]) =
            *reinterpret_cast<const float4*>(&d_MT[(c0 + mk + 8) * C + half * 128 + mo]);
        *reinterpret_cast<float4*>(&xs[xk][xn]) =
            *reinterpret_cast<const float4*>(&x[((size_t)(b * C + c0 + xk)) * NSP + n0 + xn]);
        __syncthreads();
#pragma unroll
        for (int k = 0; k < 16; k++) {
            ulonglong2 m01 = *reinterpret_cast<const ulonglong2*>(&mt[k][ccb]);
            ulonglong2 m23 = *reinterpret_cast<const ulonglong2*>(&mt[k][ccb + 4]);
            float4 xv = *reinterpret_cast<const float4*>(&xs[k][nb]);
            u64 xb0 = bcast2(xv.x), xb1 = bcast2(xv.y);
            u64 xb2 = bcast2(xv.z), xb3 = bcast2(xv.w);
            acc[0][0] = fma2(m01.x, xb0, acc[0][0]);
            acc[1][0] = fma2(m01.y, xb0, acc[1][0]);
            acc[2][0] = fma2(m23.x, xb0, acc[2][0]);
            acc[3][0] = fma2(m23.y, xb0, acc[3][0]);
            acc[0][1] = fma2(m01.x, xb1, acc[0][1]);
            acc[1][1] = fma2(m01.y, xb1, acc[1][1]);
            acc[2][1] = fma2(m23.x, xb1, acc[2][1]);
            acc[3][1] = fma2(m23.y, xb1, acc[3][1]);
            acc[0][2] = fma2(m01.x, xb2, acc[0][2]);
            acc[1][2] = fma2(m01.y, xb2, acc[1][2]);
            acc[2][2] = fma2(m23.x, xb2, acc[2][2]);
            acc[3][2] = fma2(m23.y, xb2, acc[3][2]);
            acc[0][3] = fma2(m01.x, xb3, acc[0][3]);
            acc[1][3] = fma2(m01.y, xb3, acc[1][3]);
            acc[2][3] = fma2(m23.x, xb3, acc[2][3]);
            acc[3][3] = fma2(m23.y, xb3, acc[3][3]);
        }
        __syncthreads();
    }

    ulonglong2 mb01 = *reinterpret_cast<const ulonglong2*>(&d_mb[half * 128 + ccb]);
    ulonglong2 mb23 = *reinterpret_cast<const ulonglong2*>(&d_mb[half * 128 + ccb + 4]);
#pragma unroll
    for (int j = 0; j < 4; j++) {
        int n = n0 + nb + j;
        float* hp = &d_h[((size_t)b * NSP + n) * C + half * 128 + ccb];
        ulonglong2 r0 = make_ulonglong2(add2(acc[0][j], mb01.x), add2(acc[1][j], mb01.y));
        ulonglong2 r1 = make_ulonglong2(add2(acc[2][j], mb23.x), add2(acc[3][j], mb23.y));
        *reinterpret_cast<ulonglong2*>(hp)     = r0;
        *reinterpret_cast<ulonglong2*>(hp + 4) = r1;
    }
}

// ---------------- chunk totals ----------------
__global__ void k_suf1()
{
    __shared__ int sp[CHS];
    __shared__ float sb[CHS];
    int b = blockIdx.y, ch = blockIdx.x, cc = threadIdx.x;
    int base = b * NSP + ch * CHS;
    if (cc < CHS) { sp[cc] = d_perm[base + cc]; sb[cc] = d_bsort[base + cc]; }
    __syncthreads();
    float s0 = 0.f, s1 = 0.f;
#pragma unroll 4
    for (int r = 0; r < CHS; r++) {
        float g = d_h[((size_t)b * NSP + sp[r]) * C + cc];
        s0 += g;
        s1 = fmaf(sb[r], g, s1);
    }
    d_cs0[(b * NCH + ch) * C + cc] = s0;
    d_cs1[(b * NCH + ch) * C + cc] = s1;
}

// ---------------- exclusive chunk suffix ----------------
__global__ void k_suf2()
{
    int b = blockIdx.x, cc = threadIdx.x;
    float a0 = 0.f, a1 = 0.f;
    for (int ch = NCH - 1; ch >= 0; --ch) {
        int i = (b * NCH + ch) * C + cc;
        float t0 = d_cs0[i], t1 = d_cs1[i];
        d_cs0[i] = a0; d_cs1[i] = a1;
        a0 += t0; a1 += t1;
    }
    d_T[((size_t)b * NT1 + NSP) * C + cc] = make_float2(0.f, 0.f);
}

// ---------------- full suffix arrays ----------------
__global__ void k_suf3()
{
    __shared__ int sp[CHS];
    __shared__ float sb[CHS];
    int b = blockIdx.y, ch = blockIdx.x, cc = threadIdx.x;
    int base = b * NSP + ch * CHS;
    if (cc < CHS) { sp[cc] = d_perm[base + cc]; sb[cc] = d_bsort[base + cc]; }
    __syncthreads();
    float a0 = d_cs0[(b * NCH + ch) * C + cc];
    float a1 = d_cs1[(b * NCH + ch) * C + cc];
    for (int r = CHS - 1; r >= 0; --r) {
        int rr = ch * CHS + r;
        float g = d_h[((size_t)b * NSP + sp[r]) * C + cc];
        a0 += g;
        a1 = fmaf(sb[r], g, a1);
        d_T[((size_t)b * NT1 + rr) * C + cc] = make_float2(a0, a1);
    }
}

// ---------------- binary search ----------------
__global__ void k_lb()
{
    int i = blockIdx.x * 256 + threadIdx.x;
    if (i >= BB * NSP) return;
    int b = i / NSP;
    float keyv = -d_av[i];
    const float* sb = d_bsort + b * NSP;
    int lo = 0, hi = NSP;
    while (lo < hi) {
        int mid = (lo + hi) >> 1;
        if (__ldg(sb + mid) > keyv) hi = mid; else lo = mid + 1;
    }
    d_lbi[i] = lo;
}

// ---------------- output ----------------
__global__ void __launch_bounds__(256) k_out(const float* __restrict__ x,
                                             float* __restrict__ out)
{
    __shared__ float zt[C][33];
    __shared__ float tl[32];
    __shared__ int lbl[32];
    int b = blockIdx.y, n0 = blockIdx.x * 32;
    int tid = threadIdx.x, lane = tid & 31, warp = tid >> 5;
    if (tid < 32) {
        tl[tid]  = d_av[b * NSP + n0 + tid];
        lbl[tid] = d_lbi[b * NSP + n0 + tid];
    }
    __syncthreads();
#pragma unroll
    for (int s = 0; s < 4; s++) {
        int nn = warp + s * 8;
        float t = tl[nn];
        size_t base = ((size_t)b * NT1 + lbl[nn]) * C;
#pragma unroll
        for (int it = 0; it < 8; it++) {
            int cc = it * 32 + lane;
            float2 T = d_T[base + cc];
            zt[cc][nn] = fmaf(fmaf(t, T.x, T.y), d_sc[cc], d_obias[cc]);
        }
    }
    __syncthreads();
#pragma unroll 4
    for (int r = 0; r < 32; r++) {
        int cc = warp * 32 + r;
        size_t g = ((size_t)(b * C + cc)) * NSP + n0 + lane;
        out[g] = zt[cc][lane] + x[g];
    }
}

// ---------------- launch ----------------
extern "C" void kernel_launch(void* const* d_in, const int* in_sizes, int n_in,
                              void* d_out, int out_size)
{
    const float* x       = (const float*)d_in[0];
    const float* g_w     = (const float*)d_in[1];
    const float* g_b     = (const float*)d_in[2];
    const float* theta_w = (const float*)d_in[3];
    const float* theta_b = (const float*)d_in[4];
    const float* phi_w   = (const float*)d_in[5];
    const float* phi_b   = (const float*)d_in[6];
    const float* wf_w    = (const float*)d_in[7];
    const float* wf_b    = (const float*)d_in[8];
    const float* wz_w    = (const float*)d_in[9];
    const float* wz_b    = (const float*)d_in[10];
    const float* bn_g    = (const float*)d_in[11];
    const float* bn_b    = (const float*)d_in[12];
    const float* bn_m    = (const float*)d_in[13];
    const float* bn_v    = (const float*)d_in[14];
    float* out = (float*)d_out;

    k_prep<<<1, 256>>>(theta_w, theta_b, phi_w, phi_b, wf_w, wf_b,
                       wz_w, wz_b, g_b, bn_g, bn_b, bn_m, bn_v);
    k_mt<<<64, 256>>>(g_w, wz_w);
    k_ab<<<dim3((NSP + 255) / 256, BB), 256>>>(x);
    k_uni<<<BB + GEMM_BLOCKS, 256>>>(x);
    k_lb<<<(BB * NSP + 255) / 256, 256>>>();
    k_suf1<<<dim3(NCH, BB), 256>>>();
    k_suf2<<<BB, 256>>>();
    k_suf3<<<dim3(NCH, BB), 256>>>();
    k_out<<<dim3(NSP / 32, BB), 256>>>(x, out);
}